// round 4
// baseline (speedup 1.0000x reference)
#include <cuda_runtime.h>

#define NN 100000
#define NE 1600000
#define CUT_K 320000        // int(E * 0.2)
#define EQ_CAP 2048
#define CAND_CAP 65536
#define NBLK 391            // ceil(NN/256)
#define FULL 0xFFFFFFFFu
#define GRID 1184
#define TB 256

// ---------------- device scratch (no allocations allowed) ----------------
__device__ __align__(16) float g_nh[NN * 32];    // row-normalized h
__device__ __align__(16) float g_hsA[NN * 32];   // h*norm payload, hop 0
__device__ __align__(16) float g_hsB[NN * 32];   // h*norm payload, hop 1
__device__ unsigned g_key[NE];                   // cos keys, perm (dst-sorted) order
__device__ int   g_psrc[NE];                     // src per perm slot
__device__ int   g_pe[NE];                       // original edge id per perm slot
__device__ int   g_rowstart[NN + 1];
__device__ int   g_cursor[NN];
__device__ int   g_bsum[NBLK];
__device__ float g_norm[NN];
__device__ int   g_deg[NN];
__device__ unsigned g_hist4[1024];               // 4 rounds x 256 bins
__device__ int   g_cand[CAND_CAP];               // slots matching 24-bit prefix
__device__ int   g_cand_count;
__device__ unsigned g_prefix;                    // final threshold key (per hop)

// float -> order-preserving uint (ascending); real cos keys are always > 0
__device__ __forceinline__ unsigned f2o(float f) {
    unsigned u = __float_as_uint(f);
    return (u & 0x80000000u) ? ~u : (u | 0x80000000u);
}

// In-block re-resolution of the radix-select prefix from stored histograms.
// Requires blockDim.x == 256. All threads return the same (prefix, kr).
__device__ void block_resolve(int nrounds, unsigned* s_scan, unsigned* s_out,
                              unsigned& prefix_o, unsigned& kr_o) {
    unsigned prefix = 0; unsigned kr = CUT_K;
    int t = threadIdx.x;
    for (int r = 0; r < nrounds; r++) {
        unsigned c = g_hist4[r * 256 + t];
        s_scan[t] = c;
        __syncthreads();
        #pragma unroll
        for (int o = 1; o < 256; o <<= 1) {
            unsigned x = (t >= o) ? s_scan[t - o] : 0u;
            __syncthreads();
            s_scan[t] += x;
            __syncthreads();
        }
        unsigned incl = s_scan[t], excl = incl - c;
        if (excl < kr && kr <= incl) { s_out[0] = (unsigned)t; s_out[1] = kr - excl; }
        __syncthreads();
        prefix |= s_out[0] << (24 - 8 * r);
        kr = s_out[1];
        __syncthreads();
    }
    prefix_o = prefix; kr_o = kr;
}

// ================= one-time setup: degree, norm, CSR build =================
__global__ void k_deg_zero() {
    int stride = gridDim.x * blockDim.x;
    for (int i = blockIdx.x * blockDim.x + threadIdx.x; i < NN; i += stride) g_deg[i] = 0;
}
__global__ void k_deg(const int* __restrict__ dst) {
    int stride = gridDim.x * blockDim.x;
    for (int i = blockIdx.x * blockDim.x + threadIdx.x; i < NE; i += stride)
        atomicAdd(&g_deg[dst[i]], 1);
}
__global__ void k_scan1() {
    __shared__ int s[256];
    int t = threadIdx.x;
    int i = blockIdx.x * 256 + t;
    int v = (i < NN) ? g_deg[i] : 0;
    if (i < NN) {
        float d = (float)v;
        if (d < 1.0f) d = 1.0f;
        g_norm[i] = 1.0f / sqrtf(d);
    }
    s[t] = v;
    __syncthreads();
    #pragma unroll
    for (int o = 1; o < 256; o <<= 1) {
        int x = (t >= o) ? s[t - o] : 0;
        __syncthreads();
        s[t] += x;
        __syncthreads();
    }
    if (i < NN) g_rowstart[i] = s[t] - v;
    if (t == 255) g_bsum[blockIdx.x] = s[255];
}
__global__ void k_scan2() {
    __shared__ int s[512];
    int t = threadIdx.x;
    int v = (t < NBLK) ? g_bsum[t] : 0;
    s[t] = v;
    __syncthreads();
    #pragma unroll
    for (int o = 1; o < 512; o <<= 1) {
        int x = (t >= o) ? s[t - o] : 0;
        __syncthreads();
        s[t] += x;
        __syncthreads();
    }
    if (t < NBLK) g_bsum[t] = s[t] - v;
}
__global__ void k_scan3() {
    int stride = gridDim.x * blockDim.x;
    for (int i = blockIdx.x * blockDim.x + threadIdx.x; i < NN; i += stride) {
        int r = g_rowstart[i] + g_bsum[i >> 8];
        g_rowstart[i] = r;
        g_cursor[i] = r;
    }
    if (blockIdx.x == 0 && threadIdx.x == 0) g_rowstart[NN] = NE;
}
__global__ void k_build(const int* __restrict__ src, const int* __restrict__ dst) {
    int stride = gridDim.x * blockDim.x;
    for (int e = blockIdx.x * blockDim.x + threadIdx.x; e < NE; e += stride) {
        int d = dst[e];
        int pos = atomicAdd(&g_cursor[d], 1);
        g_psrc[pos] = src[e];
        g_pe[pos] = e;
    }
}

// ======== initial prep (hop 0 only): nh, hsA from feat; clear per-launch state
__global__ void k_prep0(const float* __restrict__ feat) {
    int tid0 = blockIdx.x * blockDim.x + threadIdx.x;
    if (tid0 < 1024) g_hist4[tid0] = 0u;
    if (tid0 == 0) g_cand_count = 0;
    int stride = gridDim.x * blockDim.x;
    for (int g = tid0; g < NN * 8; g += stride) {
        int row = g >> 3;
        float nm = g_norm[row];
        float4 v = ((const float4*)feat)[g];
        float ss = v.x * v.x + v.y * v.y + v.z * v.z + v.w * v.w;
        #pragma unroll
        for (int o = 4; o; o >>= 1) ss += __shfl_xor_sync(FULL, ss, o);
        float inv = 1.0f / fmaxf(sqrtf(ss), 1e-12f);
        ((float4*)g_nh)[g]  = make_float4(v.x * inv, v.y * inv, v.z * inv, v.w * inv);
        ((float4*)g_hsA)[g] = make_float4(v.x * nm,  v.y * nm,  v.z * nm,  v.w * nm);
    }
}

// ======== cosine, warp-per-node in perm order; fused round-1 histogram
__global__ void k_cos() {
    __shared__ unsigned sh[256];
    for (int i = threadIdx.x; i < 256; i += TB) sh[i] = 0u;
    __syncthreads();
    int lane = threadIdx.x & 31;
    int nwarps = gridDim.x * (TB >> 5);
    for (int w = blockIdx.x * (TB >> 5) + (threadIdx.x >> 5); w < NN; w += nwarps) {
        int beg = g_rowstart[w], end = g_rowstart[w + 1];
        if (beg == end) continue;
        float b = g_nh[w * 32 + lane];         // dst row held in registers
        for (int base = beg; base < end; base += 32) {
            int idx = base + lane;
            int n = end - base; if (n > 32) n = 32;
            int sL = (idx < end) ? g_psrc[idx] : 0;
            float kout = 0.0f;
            for (int i = 0; i < n; i++) {
                int s = __shfl_sync(FULL, sL, i);
                float p = g_nh[s * 32 + lane] * b;
                #pragma unroll
                for (int o = 16; o; o >>= 1) p += __shfl_xor_sync(FULL, p, o);
                if (i == lane) kout = p;       // lane i keeps edge i's cos
            }
            if (lane < n) {
                unsigned key = f2o(kout);
                g_key[idx] = key;              // coalesced store, perm order
                atomicAdd(&sh[key >> 24], 1u);
            }
        }
    }
    __syncthreads();
    for (int i = threadIdx.x; i < 256; i += TB)
        if (sh[i]) atomicAdd(&g_hist4[i], sh[i]);
}

// ======== radix histogram round r (prologue re-resolves rounds 0..r-1)
__global__ void k_hist(int r, int shift, unsigned mask, int collect) {
    __shared__ unsigned s_scan[256];
    __shared__ unsigned s_out[2];
    __shared__ unsigned sh[256];
    unsigned prefix, kr;
    block_resolve(r, s_scan, s_out, prefix, kr);
    for (int i = threadIdx.x; i < 256; i += TB) sh[i] = 0u;
    __syncthreads();
    int stride = gridDim.x * blockDim.x;
    for (int j = blockIdx.x * blockDim.x + threadIdx.x; j < NE; j += stride) {
        unsigned key = g_key[j];
        if ((key & mask) == (prefix & mask)) {
            atomicAdd(&sh[(key >> shift) & 255u], 1u);
            if (collect) {
                int pos = atomicAdd(&g_cand_count, 1);
                if (pos < CAND_CAP) g_cand[pos] = j;
            }
        }
    }
    __syncthreads();
    for (int i = threadIdx.x; i < 256; i += TB)
        if (sh[i]) atomicAdd(&g_hist4[r * 256 + i], sh[i]);
}

// ======== tie resolution: drop kr lowest-original-index equal-key edges by
//          rewriting their keys to 0; publish final prefix; clear for next hop
__global__ void k_eq_mark() {
    __shared__ unsigned s_scan[256];
    __shared__ unsigned s_out[2];
    __shared__ int s_list[EQ_CAP];
    __shared__ int s_pe[EQ_CAP];
    __shared__ int s_n;
    int t = threadIdx.x;
    unsigned prefix, kr;
    block_resolve(4, s_scan, s_out, prefix, kr);
    if (t == 0) s_n = 0;
    __syncthreads();
    int cc = g_cand_count;
    if (cc <= CAND_CAP) {
        for (int i = t; i < cc; i += TB) {
            int j = g_cand[i];
            if (g_key[j] == prefix) {
                int p = atomicAdd(&s_n, 1);
                if (p < EQ_CAP) { s_list[p] = j; s_pe[p] = g_pe[j]; }
            }
        }
    } else {
        for (int j = t; j < NE; j += TB) {     // pathological fallback
            if (g_key[j] == prefix) {
                int p = atomicAdd(&s_n, 1);
                if (p < EQ_CAP) { s_list[p] = j; s_pe[p] = g_pe[j]; }
            }
        }
    }
    __syncthreads();
    int n = s_n; if (n > EQ_CAP) n = EQ_CAP;
    for (int i = t; i < n; i += TB) {
        int e = s_pe[i];
        int rank = 0;
        for (int m = 0; m < n; m++) rank += (s_pe[m] < e);
        if (rank < (int)kr) g_key[s_list[i]] = 0u;   // below any real key
    }
    __syncthreads();
    if (t == 0) { g_prefix = prefix; g_cand_count = 0; }
    for (int i = t; i < 1024; i += TB) g_hist4[i] = 0u;   // ready for next hop
}

// ======== aggregation, hop 0: acc = sum(kept hsA[src]); fused next-hop prep
__global__ void k_agg_mid() {
    int lane = threadIdx.x & 31;
    int nwarps = gridDim.x * (TB >> 5);
    unsigned thr = g_prefix;
    for (int w = blockIdx.x * (TB >> 5) + (threadIdx.x >> 5); w < NN; w += nwarps) {
        int beg = g_rowstart[w], end = g_rowstart[w + 1];
        float acc = 0.0f;
        for (int base = beg; base < end; base += 32) {
            int idx = base + lane;
            unsigned kL = (idx < end) ? g_key[idx] : 0u;
            int sL = (idx < end) ? g_psrc[idx] : 0;
            #pragma unroll
            for (int i = 0; i < 32; i++) {
                unsigned k = __shfl_sync(FULL, kL, i);
                if (k >= thr) {
                    int s = __shfl_sync(FULL, sL, i);
                    acc += g_hsA[s * 32 + lane];
                }
            }
        }
        float nm = g_norm[w];
        float v = acc * nm;                  // trailing norm -> next hop's h
        float ss = v * v;
        #pragma unroll
        for (int o = 16; o; o >>= 1) ss += __shfl_xor_sync(FULL, ss, o);
        float inv = 1.0f / fmaxf(sqrtf(ss), 1e-12f);
        g_nh[w * 32 + lane]  = v * inv;
        g_hsB[w * 32 + lane] = v * nm;       // leading norm for hop-1 messages
    }
}

// ======== aggregation, hop 1: acc = sum(kept hsB[src]); fused norm + FC
__global__ void k_agg_out(const float* __restrict__ W, float* __restrict__ out) {
    __shared__ float sW[32 * 33];
    for (int i = threadIdx.x; i < 1024; i += TB) sW[(i >> 5) * 33 + (i & 31)] = W[i];
    __syncthreads();
    int lane = threadIdx.x & 31;
    int nwarps = gridDim.x * (TB >> 5);
    unsigned thr = g_prefix;
    for (int w = blockIdx.x * (TB >> 5) + (threadIdx.x >> 5); w < NN; w += nwarps) {
        int beg = g_rowstart[w], end = g_rowstart[w + 1];
        float acc = 0.0f;
        for (int base = beg; base < end; base += 32) {
            int idx = base + lane;
            unsigned kL = (idx < end) ? g_key[idx] : 0u;
            int sL = (idx < end) ? g_psrc[idx] : 0;
            #pragma unroll
            for (int i = 0; i < 32; i++) {
                unsigned k = __shfl_sync(FULL, kL, i);
                if (k >= thr) {
                    int s = __shfl_sync(FULL, sL, i);
                    acc += g_hsB[s * 32 + lane];
                }
            }
        }
        float hv = acc * g_norm[w];          // trailing norm
        float o2 = 0.0f;
        #pragma unroll
        for (int k = 0; k < 32; k++)
            o2 += __shfl_sync(FULL, hv, k) * sW[lane * 33 + k];
        out[w * 32 + lane] = o2;
    }
}

extern "C" void kernel_launch(void* const* d_in, const int* in_sizes, int n_in,
                              void* d_out, int out_size) {
    const float* feat = (const float*)d_in[0];
    const float* W    = (const float*)d_in[1];
    const int*   src  = (const int*)d_in[2];
    const int*   dst  = (const int*)d_in[3];
    float* out = (float*)d_out;

    // one-time CSR build (dst is input-invariant)
    k_deg_zero<<<GRID, TB>>>();
    k_deg<<<GRID, TB>>>(dst);
    k_scan1<<<NBLK, 256>>>();
    k_scan2<<<1, 512>>>();
    k_scan3<<<GRID, TB>>>();
    k_build<<<GRID, TB>>>(src, dst);

    k_prep0<<<GRID, TB>>>(feat);

    // ---- hop 0 ----
    k_cos<<<GRID, TB>>>();
    k_hist<<<GRID, TB>>>(1, 16, 0xFF000000u, 0);
    k_hist<<<GRID, TB>>>(2,  8, 0xFFFF0000u, 0);
    k_hist<<<GRID, TB>>>(3,  0, 0xFFFFFF00u, 1);
    k_eq_mark<<<1, TB>>>();
    k_agg_mid<<<GRID, TB>>>();

    // ---- hop 1 ----
    k_cos<<<GRID, TB>>>();
    k_hist<<<GRID, TB>>>(1, 16, 0xFF000000u, 0);
    k_hist<<<GRID, TB>>>(2,  8, 0xFFFF0000u, 0);
    k_hist<<<GRID, TB>>>(3,  0, 0xFFFFFF00u, 1);
    k_eq_mark<<<1, TB>>>();
    k_agg_out<<<GRID, TB>>>(W, out);
}

// round 5
// speedup vs baseline: 1.6522x; 1.6522x over previous
#include <cuda_runtime.h>

#define NN 100000
#define NE 1600000
#define D 32
#define CUT_K 320000        // int(E * 0.2)
#define EQ_CAP 2048
#define CAND_CAP 65536
#define FULL 0xFFFFFFFFu
#define TB 256

// ---------------- device scratch (no allocations allowed) ----------------
__device__ __align__(16) float g_nh[NN * D];     // row-normalized h
__device__ __align__(16) float g_hs[NN * D];     // h * norm  (message payload)
__device__ __align__(16) float g_hnew[NN * D];   // aggregation target
__device__ unsigned g_key[NE];                   // order-preserving cos keys (edge order)
__device__ float g_norm[NN];
__device__ int   g_deg[NN];
__device__ unsigned g_hist4[1024];               // 4 rounds x 256 bins
__device__ int   g_cand[CAND_CAP];               // slots matching 24-bit prefix
__device__ int   g_cand_count;
__device__ unsigned g_prefix;                    // final threshold key (per hop)

// float -> order-preserving uint (ascending); all real keys > 0
__device__ __forceinline__ unsigned f2o(float f) {
    unsigned u = __float_as_uint(f);
    return (u & 0x80000000u) ? ~u : (u | 0x80000000u);
}

// In-block re-resolution of the radix-select prefix from stored histograms.
// Requires blockDim.x == 256. All threads return the same (prefix, kr).
__device__ void block_resolve(int nrounds, unsigned* s_scan, unsigned* s_out,
                              unsigned& prefix_o, unsigned& kr_o) {
    unsigned prefix = 0; unsigned kr = CUT_K;
    int t = threadIdx.x;
    for (int r = 0; r < nrounds; r++) {
        unsigned c = g_hist4[r * 256 + t];
        s_scan[t] = c;
        __syncthreads();
        #pragma unroll
        for (int o = 1; o < 256; o <<= 1) {
            unsigned x = (t >= o) ? s_scan[t - o] : 0u;
            __syncthreads();
            s_scan[t] += x;
            __syncthreads();
        }
        unsigned incl = s_scan[t], excl = incl - c;
        if (excl < kr && kr <= incl) { s_out[0] = (unsigned)t; s_out[1] = kr - excl; }
        __syncthreads();
        prefix |= s_out[0] << (24 - 8 * r);
        kr = s_out[1];
        __syncthreads();
    }
    prefix_o = prefix; kr_o = kr;
}

// ================= setup: degree, norm (once per launch) =================
__global__ void k_deg_zero() {
    int i = blockIdx.x * blockDim.x + threadIdx.x;
    if (i < NN) g_deg[i] = 0;
}
__global__ void k_deg(const int* __restrict__ dst) {
    int i = blockIdx.x * blockDim.x + threadIdx.x;
    if (i < NE) atomicAdd(&g_deg[dst[i]], 1);
}
__global__ void k_norm() {
    int i = blockIdx.x * blockDim.x + threadIdx.x;
    if (i < NN) {
        float d = (float)g_deg[i];
        if (d < 1.0f) d = 1.0f;
        g_norm[i] = 1.0f / sqrtf(d);
    }
    if (i < 1024) g_hist4[i] = 0u;
    if (i == 0) g_cand_count = 0;
}

// ---- per-hop prep: 8 lanes/row, float4. nh, hs; also zeroes h_new for scatter
__global__ void k_prep(const float* __restrict__ feat, int hop) {
    int g = blockIdx.x * blockDim.x + threadIdx.x;
    int row = g >> 3, sub = g & 7;
    if (row >= NN) return;
    float nm = g_norm[row];
    float4 v;
    if (hop) {
        v = ((const float4*)g_hnew)[g];
        v.x *= nm; v.y *= nm; v.z *= nm; v.w *= nm;   // trailing norm, prev hop
    } else {
        v = ((const float4*)feat)[g];
    }
    ((float4*)g_hnew)[g] = make_float4(0.f, 0.f, 0.f, 0.f);  // ready for scatter
    float ss = v.x * v.x + v.y * v.y + v.z * v.z + v.w * v.w;
    #pragma unroll
    for (int o = 4; o; o >>= 1) ss += __shfl_xor_sync(FULL, ss, o);
    float inv = 1.0f / fmaxf(sqrtf(ss), 1e-12f);
    ((float4*)g_nh)[g] = make_float4(v.x * inv, v.y * inv, v.z * inv, v.w * inv);
    ((float4*)g_hs)[g] = make_float4(v.x * nm,  v.y * nm,  v.z * nm,  v.w * nm);
}

// ---- cosine per edge (8 lanes/edge, float4) + fused radix round-1 histogram
__global__ void k_cos(const int* __restrict__ src, const int* __restrict__ dst) {
    __shared__ unsigned sh[256];
    for (int i = threadIdx.x; i < 256; i += TB) sh[i] = 0u;
    __syncthreads();
    int g = blockIdx.x * blockDim.x + threadIdx.x;
    int e = g >> 3, sub = g & 7;
    float p = 0.0f;
    if (e < NE) {
        int s = src[e], d = dst[e];
        float4 a = ((const float4*)g_nh)[s * 8 + sub];
        float4 b = ((const float4*)g_nh)[d * 8 + sub];
        p = a.x * b.x + a.y * b.y + a.z * b.z + a.w * b.w;
    }
    #pragma unroll
    for (int o = 4; o; o >>= 1) p += __shfl_xor_sync(FULL, p, o);
    if (e < NE && sub == 0) {
        unsigned key = f2o(p);
        g_key[e] = key;
        atomicAdd(&sh[key >> 24], 1u);
    }
    __syncthreads();
    for (int i = threadIdx.x; i < 256; i += TB)
        if (sh[i]) atomicAdd(&g_hist4[i], sh[i]);
}

// ---- radix histogram round r (prologue re-resolves rounds 0..r-1)
__global__ void k_hist(int r, int shift, unsigned mask, int collect) {
    __shared__ unsigned s_scan[256];
    __shared__ unsigned s_out[2];
    __shared__ unsigned sh[256];
    unsigned prefix, kr;
    block_resolve(r, s_scan, s_out, prefix, kr);
    for (int i = threadIdx.x; i < 256; i += TB) sh[i] = 0u;
    __syncthreads();
    int stride = gridDim.x * blockDim.x;
    for (int e = blockIdx.x * blockDim.x + threadIdx.x; e < NE; e += stride) {
        unsigned key = g_key[e];
        if ((key & mask) == (prefix & mask)) {
            atomicAdd(&sh[(key >> shift) & 255u], 1u);
            if (collect) {
                int pos = atomicAdd(&g_cand_count, 1);
                if (pos < CAND_CAP) g_cand[pos] = e;
            }
        }
    }
    __syncthreads();
    for (int i = threadIdx.x; i < 256; i += TB)
        if (sh[i]) atomicAdd(&g_hist4[r * 256 + i], sh[i]);
}

// ---- tie resolution: drop kr lowest-index equal-key edges (rewrite key to 0);
//      publish final prefix; reset hist/cand for next hop
__global__ void k_eq_mark() {
    __shared__ unsigned s_scan[256];
    __shared__ unsigned s_out[2];
    __shared__ int s_list[EQ_CAP];
    __shared__ int s_n;
    int t = threadIdx.x;
    unsigned prefix, kr;
    block_resolve(4, s_scan, s_out, prefix, kr);
    if (t == 0) s_n = 0;
    __syncthreads();
    int cc = g_cand_count;
    if (cc <= CAND_CAP) {
        for (int i = t; i < cc; i += TB) {
            int e = g_cand[i];
            if (g_key[e] == prefix) {
                int p = atomicAdd(&s_n, 1);
                if (p < EQ_CAP) s_list[p] = e;
            }
        }
    } else {
        for (int e = t; e < NE; e += TB) {     // pathological fallback
            if (g_key[e] == prefix) {
                int p = atomicAdd(&s_n, 1);
                if (p < EQ_CAP) s_list[p] = e;
            }
        }
    }
    __syncthreads();
    int n = s_n; if (n > EQ_CAP) n = EQ_CAP;
    for (int i = t; i < n; i += TB) {
        int e = s_list[i];
        int rank = 0;
        for (int m = 0; m < n; m++) rank += (s_list[m] < e);
        if (rank < (int)kr) g_key[e] = 0u;     // below any real key
    }
    __syncthreads();
    if (t == 0) { g_prefix = prefix; g_cand_count = 0; }
    for (int i = t; i < 1024; i += TB) g_hist4[i] = 0u;   // ready for next hop
}

// ---- message scatter (8 lanes/edge, float4 gather, red.v4 accumulate)
__global__ void k_scatter(const int* __restrict__ src, const int* __restrict__ dst) {
    int g = blockIdx.x * blockDim.x + threadIdx.x;
    int e = g >> 3, sub = g & 7;
    if (e >= NE) return;
    if (g_key[e] < g_prefix) return;           // dropped ties have key==0
    int s = src[e], d = dst[e];
    float4 v = ((const float4*)g_hs)[s * 8 + sub];
    float* p = &g_hnew[d * D + sub * 4];
    asm volatile("red.global.add.v4.f32 [%0], {%1, %2, %3, %4};"
                 :: "l"(p), "f"(v.x), "f"(v.y), "f"(v.z), "f"(v.w) : "memory");
}

// ---- final: out = (h_new * norm) @ W^T ----------------
__global__ void k_out(const float* __restrict__ W, float* __restrict__ out) {
    __shared__ float sW[32 * 33];
    for (int i = threadIdx.x; i < 1024; i += TB) {
        int o = i >> 5, k = i & 31;
        sW[o * 33 + k] = W[i];
    }
    __syncthreads();
    int g = blockIdx.x * blockDim.x + threadIdx.x;
    int row = g >> 5, lane = g & 31;
    if (row >= NN) return;
    float hv = g_hnew[row * D + lane] * g_norm[row];
    float acc = 0.0f;
    #pragma unroll
    for (int k = 0; k < 32; k++) {
        float hk = __shfl_sync(FULL, hv, k);
        acc += hk * sW[lane * 33 + k];
    }
    out[row * D + lane] = acc;
}

extern "C" void kernel_launch(void* const* d_in, const int* in_sizes, int n_in,
                              void* d_out, int out_size) {
    const float* feat = (const float*)d_in[0];
    const float* W    = (const float*)d_in[1];
    const int*   src  = (const int*)d_in[2];
    const int*   dst  = (const int*)d_in[3];
    float* out = (float*)d_out;

    const int grid_node  = (NN + TB - 1) / TB;
    const int grid_edge  = (NE + TB - 1) / TB;
    const int grid_row8  = (NN * 8 + TB - 1) / TB;
    const int grid_edge8 = (NE * 8 + TB - 1) / TB;
    const int grid_rowW  = (NN * 32 + TB - 1) / TB;

    k_deg_zero<<<grid_node, TB>>>();
    k_deg<<<grid_edge, TB>>>(dst);
    k_norm<<<grid_node, TB>>>();

    for (int hop = 0; hop < 2; hop++) {
        k_prep<<<grid_row8, TB>>>(feat, hop);
        k_cos<<<grid_edge8, TB>>>(src, dst);   // + fused round-1 histogram

        k_hist<<<2048, TB>>>(1, 16, 0xFF000000u, 0);
        k_hist<<<2048, TB>>>(2,  8, 0xFFFF0000u, 0);
        k_hist<<<2048, TB>>>(3,  0, 0xFFFFFF00u, 1);   // + candidate collection
        k_eq_mark<<<1, TB>>>();

        k_scatter<<<grid_edge8, TB>>>(src, dst);
    }

    k_out<<<grid_rowW, TB>>>(W, out);
}